// round 11
// baseline (speedup 1.0000x reference)
#include <cuda_runtime.h>
#include <cuda_fp16.h>
#include <cstdint>

#define NN 50000
#define NE 600000
#define H  128
#define HV4 32          // H/4
#define GG 16
#define OUTD 14
#define NL 3
#define GEN_EPS 1e-7f
#define BN_EPS  1e-5f
#define BN_BLOCKS 256
#define BN_CHUNK  196     // ceil(50000/256)
#define NBC 391           // ceil(NN/128)  (embed / gemm blocks)
#define NSB 196           // ceil(NN/256)  (scan blocks)
#define NEB 2344          // ceil(NE/256)
#define MAXPART 800
#define LOG2E 1.4426950408889634f

// ---------------- scratch (device globals; no allocation allowed) ------------
__device__ float  g_hv [NN * H];
__device__ float  g_h1f[NN * H];              // hv1 = relu(bn(hv)), fp32
__device__ __align__(16) uint2  g_xh [NN * HV4];   // x fp16 (GEMM A)
__device__ __align__(16) __half g_wh [NL * H * H]; // W^T fp16 [l][n][k]
__device__ int    g_cnt[NN];
__device__ int    g_off[NN];
__device__ int    g_bsum[NSB];
__device__ int    g_boff[NSB];
__device__ int    g_edge[NE];                 // packed: src | (f0*3+f1)<<16
__device__ float  g_part[2][MAXPART][H];
__device__ float  g_scale[H];
__device__ float  g_shift[H];
__device__ float  g_etab[18 * H];
__device__ float  g_hg[GG * H];
__device__ int    g_cntg[GG];
__device__ int    g_sync[8];

__device__ __forceinline__ uint32_t su32(const void* p) {
    uint32_t a;
    asm("{ .reg .u64 t; cvta.to.shared.u64 t, %1; cvt.u32.u64 %0, t; }" : "=r"(a) : "l"(p));
    return a;
}

// ------- BN finalize + edge table, 256-thread block-inline version -----------
__device__ void bnfin_body(const float* __restrict__ gamma, const float* __restrict__ bnb,
                           const float* __restrict__ ee0, const float* __restrict__ ee1,
                           int l, float* red) {
    int tid = threadIdx.x;
    int c = tid & 127, g = tid >> 7;
    float s = 0.f, ss = 0.f;
    for (int b = g; b < NBC; b += 2) { s += g_part[0][b][c]; ss += g_part[1][b][c]; }
    red[g * 128 + c]       = s;
    red[256 + g * 128 + c] = ss;
    __syncthreads();
    if (tid < H) {
        float S  = red[tid]       + red[128 + tid];
        float SS = red[256 + tid] + red[384 + tid];
        float mu  = S / (float)NN;
        float var = fmaxf(SS / (float)NN - mu * mu, 0.f);
        float sc  = rsqrtf(var + BN_EPS) * gamma[l * H + tid];
        g_scale[tid] = sc;
        g_shift[tid] = bnb[l * H + tid] - mu * sc;
    }
    for (int i = tid; i < 18 * H; i += 256) {
        int idx = i >> 7, cc = i & 127;
        int f0 = idx / 3, f1 = idx - f0 * 3;
        g_etab[i] = ee0[(l * 6 + f0) * H + cc] + ee1[(l * 3 + f1) * H + cc];
    }
}

// ---- embed (+BN stats, g_cnt zero) for blocks<NBC; W^T transpose after ------
__global__ void k_embed(const int* __restrict__ f0, const int* __restrict__ f1,
                        const float* __restrict__ W0, const float* __restrict__ W1,
                        const float* __restrict__ W) {
    int b = blockIdx.x, tid = threadIdx.x;
    if (b == 0 && tid < 8) g_sync[tid] = 0;
    if (b < NBC) {
        __shared__ int sf0[128], sf1[128];
        int c = tid;
        int n0 = b * 128;
        int cnt = min(128, NN - n0);
        if (c < cnt) {
            sf0[c] = f0[n0 + c]; sf1[c] = f1[n0 + c];
            g_cnt[n0 + c] = 0;
        }
        __syncthreads();
        float s = 0.f, ss = 0.f;
        for (int i = 0; i < cnt; i++) {
            float v = W0[sf0[i] * H + c] + W1[sf1[i] * H + c];
            g_hv[(n0 + i) * H + c] = v;
            s += v; ss += v * v;
        }
        g_part[0][b][c] = s;
        g_part[1][b][c] = ss;
    } else {
        __shared__ float t[32][33];
        int bi = b - NBC;
        int l = bi >> 4, r = bi & 15;
        int bk = r >> 2, bn = r & 3;
        int tx = tid & 31, ty = tid >> 5;
        const float* Wl = W + (size_t)l * H * H;
#pragma unroll
        for (int i = 0; i < 8; i++)
            t[ty + i * 4][tx] = Wl[(bk * 32 + ty + i * 4) * H + bn * 32 + tx];
        __syncthreads();
        __half* out = g_wh + (size_t)l * H * H;
#pragma unroll
        for (int i = 0; i < 8; i++)
            out[(bn * 32 + ty + i * 4) * H + bk * 32 + tx] = __float2half(t[tx][ty + i * 4]);
    }
}

// ---------------- CSR build --------------------------------------------------
__global__ void k_count(const int* __restrict__ dst) {
    int e = blockIdx.x * blockDim.x + threadIdx.x;
    if (e < NE) atomicAdd(&g_cnt[dst[e]], 1);
    if (blockIdx.x == 0) {
        for (int i = threadIdx.x; i < GG * H; i += 256) g_hg[i] = 0.f;
        if (threadIdx.x < GG) g_cntg[threadIdx.x] = 0;
    }
}

__global__ void k_scan12() {
    __shared__ int wsum[8];
    __shared__ int sm[256];
    __shared__ int flag;
    int b = blockIdx.x, t = threadIdx.x;
    int idx = b * 256 + t;
    int v = (idx < NN) ? g_cnt[idx] : 0;
    int s = v;
    for (int d = 16; d > 0; d >>= 1) s += __shfl_down_sync(0xffffffffu, s, d);
    if ((t & 31) == 0) wsum[t >> 5] = s;
    __syncthreads();
    if (t == 0) {
        int bs = 0;
#pragma unroll
        for (int w = 0; w < 8; w++) bs += wsum[w];
        g_bsum[b] = bs;
        __threadfence();
        int old = atomicAdd(&g_sync[0], 1);
        flag = (old == NSB - 1);
    }
    __syncthreads();
    if (flag) {
        int v2 = (t < NSB) ? g_bsum[t] : 0;
        sm[t] = v2;
        __syncthreads();
        for (int d = 1; d < 256; d <<= 1) {
            int u = (t >= d) ? sm[t - d] : 0;
            __syncthreads();
            sm[t] += u;
            __syncthreads();
        }
        if (t < NSB) g_boff[t] = sm[t] - v2;
    }
}

__global__ void k_scan3() {
    __shared__ int wsum[8];
    int b = blockIdx.x, t = threadIdx.x;
    int idx = b * 256 + t;
    int v = (idx < NN) ? g_cnt[idx] : 0;
    int inc = v;
    for (int d = 1; d < 32; d <<= 1) {
        int u = __shfl_up_sync(0xffffffffu, inc, d);
        if ((t & 31) >= d) inc += u;
    }
    if ((t & 31) == 31) wsum[t >> 5] = inc;
    __syncthreads();
    int w = t >> 5;
    int woff = 0;
#pragma unroll
    for (int i = 0; i < 8; i++) if (i < w) woff += wsum[i];
    if (idx < NN) g_off[idx] = g_boff[b] + woff + inc - v;
}

// scatter edges (g_off as cursor) + layer-0 bnfin in the extra block ----------
__global__ void k_scatter(const int* __restrict__ src, const int* __restrict__ dst,
                          const int* __restrict__ f0, const int* __restrict__ f1,
                          const float* __restrict__ gamma, const float* __restrict__ bnb,
                          const float* __restrict__ ee0, const float* __restrict__ ee1) {
    int b = blockIdx.x;
    if (b < NEB) {
        int e = b * 256 + threadIdx.x;
        if (e >= NE) return;
        int d = dst[e];
        int j = atomicAdd(&g_off[d], 1);
        g_edge[j] = src[e] | ((f0[e] * 3 + f1[e]) << 16);
    } else {
        __shared__ float red[512];
        bnfin_body(gamma, bnb, ee0, ee1, 0, red);
    }
}

// ---------------- BN apply -> fp32 hv1 buffer --------------------------------
__global__ void k_bnh() {
    int i = blockIdx.x * blockDim.x + threadIdx.x;   // over NN*HV4
    if (i >= NN * HV4) return;
    int q = i & 31;
    float4 v  = ((const float4*)g_hv)[i];
    float4 sc = ((const float4*)g_scale)[q];
    float4 sh = ((const float4*)g_shift)[q];
    float4 r;
    r.x = fmaxf(fmaf(v.x, sc.x, sh.x), 0.f);
    r.y = fmaxf(fmaf(v.y, sc.y, sh.y), 0.f);
    r.z = fmaxf(fmaf(v.z, sc.z, sh.z), 0.f);
    r.w = fmaxf(fmaf(v.w, sc.w, sh.w), 0.f);
    ((float4*)g_h1f)[i] = r;
}

// ---------------- GENConv aggregation: warp per dst node ---------------------
// t = max(hv1+e, 0); x = exp2(t*c1 + c2)  [= exp((t+eps)*beta)]
// agg = sum(t*x)/sum(x) + eps  (exact identity);  x_out = hv1 + agg, fp16.
__global__ void __launch_bounds__(256) k_agg(const float* __restrict__ beta, int l) {
    __shared__ float etab[18 * H];
    int tid = threadIdx.x;
    for (int i = tid; i < 18 * H; i += 256) etab[i] = g_etab[i];
    __syncthreads();
    int gt   = blockIdx.x * 256 + tid;
    int wid  = gt >> 5;
    int lane = tid & 31;
    if (wid >= NN) return;
    float c1 = beta[l] * LOG2E;
    float c2 = GEN_EPS * c1;
    int end = g_off[wid];
    int beg = end - g_cnt[wid];
    const float4* __restrict__ hv4 = (const float4*)g_h1f;
    const float4* __restrict__ et4 = (const float4*)etab;
    float4 num = make_float4(0.f, 0.f, 0.f, 0.f);
    float4 den = make_float4(0.f, 0.f, 0.f, 0.f);
#define EDGE_ELEM(hc, ec, nc, dc) do {                                    \
        float t_ = fmaxf((hc) + (ec), 0.f);                               \
        float z_ = fmaf(t_, c1, c2);                                      \
        float x_;                                                         \
        asm("ex2.approx.f32 %0, %1;" : "=f"(x_) : "f"(z_));               \
        dc += x_; nc = fmaf(t_, x_, nc); } while (0)
#define EDGE_ONE(pe) do {                                                 \
        int src_ = (pe) & 0xFFFF;                                         \
        int idx_ = (pe) >> 16;                                            \
        float4 h_ = hv4[src_ * HV4 + lane];                               \
        float4 e_ = et4[idx_ * HV4 + lane];                               \
        EDGE_ELEM(h_.x, e_.x, num.x, den.x);                              \
        EDGE_ELEM(h_.y, e_.y, num.y, den.y);                              \
        EDGE_ELEM(h_.z, e_.z, num.z, den.z);                              \
        EDGE_ELEM(h_.w, e_.w, num.w, den.w); } while (0)
    int j = beg;
    for (; j + 2 <= end; j += 2) {
        int pe0 = g_edge[j], pe1 = g_edge[j + 1];
        EDGE_ONE(pe0);
        EDGE_ONE(pe1);
    }
    if (j < end) { int pe0 = g_edge[j]; EDGE_ONE(pe0); }
    float4 xo = hv4[wid * HV4 + lane];
    if (end > beg) {
        xo.x += num.x / den.x + GEN_EPS;
        xo.y += num.y / den.y + GEN_EPS;
        xo.z += num.z / den.z + GEN_EPS;
        xo.w += num.w / den.w + GEN_EPS;
    }
    __half2 p0 = __floats2half2_rn(xo.x, xo.y);
    __half2 p1 = __floats2half2_rn(xo.z, xo.w);
    uint2 o;
    o.x = *(unsigned int*)&p0;
    o.y = *(unsigned int*)&p1;
    g_xh[wid * HV4 + lane] = o;
}

// --- MLP GEMM via HMMA: hv = x@W + b + hv, + BN stats, + next-layer bnfin ----
__global__ void __launch_bounds__(256) k_gemm(const __half* __restrict__ Wt,
                                              const float* __restrict__ bias,
                                              const float* __restrict__ gamma,
                                              const float* __restrict__ bnb,
                                              const float* __restrict__ ee0,
                                              const float* __restrict__ ee1,
                                              int l) {
    __shared__ __align__(16) __half As[128 * 72];
    __shared__ __align__(16) __half Bs[128 * 72];
    __shared__ int flagg;
    int tid = threadIdx.x;
    int warp = tid >> 5, lane = tid & 31;
    int row0 = blockIdx.x * 128;
    const __half* xh = (const __half*)g_xh;

    float acc[16][4];
#pragma unroll
    for (int t = 0; t < 16; t++)
#pragma unroll
        for (int j = 0; j < 4; j++) acc[t][j] = 0.f;

#pragma unroll
    for (int kk = 0; kk < H; kk += 64) {
#pragma unroll
        for (int i = 0; i < 4; i++) {
            int f = tid + i * 256;
            int r = f >> 3, c8 = f & 7;
            uint4 v = make_uint4(0, 0, 0, 0);
            if (row0 + r < NN) v = ((const uint4*)(xh + (size_t)(row0 + r) * H + kk))[c8];
            *(uint4*)&As[r * 72 + c8 * 8] = v;
            uint4 w = ((const uint4*)(Wt + r * H + kk))[c8];
            *(uint4*)&Bs[r * 72 + c8 * 8] = w;
        }
        __syncthreads();
        uint32_t a_row = su32(&As[(warp * 16 + (lane & 15)) * 72 + ((lane >> 4) * 8)]);
#pragma unroll
        for (int k = 0; k < 4; k++) {
            uint32_t a0, a1, a2, a3;
            asm volatile("ldmatrix.sync.aligned.m8n8.x4.shared.b16 {%0,%1,%2,%3}, [%4];"
                         : "=r"(a0), "=r"(a1), "=r"(a2), "=r"(a3)
                         : "r"(a_row + k * 32));
#pragma unroll
            for (int p = 0; p < 8; p++) {
                int brow = p * 16 + ((lane >> 4) << 3) + (lane & 7);
                int bcol = k * 16 + ((lane >> 3) & 1) * 8;
                uint32_t baddr = su32(&Bs[brow * 72 + bcol]);
                uint32_t b0, b1, b2, b3;
                asm volatile("ldmatrix.sync.aligned.m8n8.x4.shared.b16 {%0,%1,%2,%3}, [%4];"
                             : "=r"(b0), "=r"(b1), "=r"(b2), "=r"(b3)
                             : "r"(baddr));
                asm volatile("mma.sync.aligned.m16n8k16.row.col.f32.f16.f16.f32 "
                             "{%0,%1,%2,%3}, {%4,%5,%6,%7}, {%8,%9}, {%0,%1,%2,%3};"
                             : "+f"(acc[2 * p][0]), "+f"(acc[2 * p][1]),
                               "+f"(acc[2 * p][2]), "+f"(acc[2 * p][3])
                             : "r"(a0), "r"(a1), "r"(a2), "r"(a3), "r"(b0), "r"(b1));
                asm volatile("mma.sync.aligned.m16n8k16.row.col.f32.f16.f16.f32 "
                             "{%0,%1,%2,%3}, {%4,%5,%6,%7}, {%8,%9}, {%0,%1,%2,%3};"
                             : "+f"(acc[2 * p + 1][0]), "+f"(acc[2 * p + 1][1]),
                               "+f"(acc[2 * p + 1][2]), "+f"(acc[2 * p + 1][3])
                             : "r"(a0), "r"(a1), "r"(a2), "r"(a3), "r"(b2), "r"(b3));
            }
        }
        __syncthreads();
    }
    float* sm_s  = (float*)As;
    float* sm_ss = (float*)Bs;
    int q = lane & 3, tq = lane >> 2;
    int r0 = row0 + warp * 16 + tq;
    int r1 = r0 + 8;
#pragma unroll
    for (int nt = 0; nt < 16; nt++) {
        int c = nt * 8 + 2 * q;
        float2 bb = *(const float2*)&bias[c];
        float v00 = 0.f, v01 = 0.f, v10 = 0.f, v11 = 0.f;
        if (r0 < NN) {
            float2* h = (float2*)&g_hv[(size_t)r0 * H + c];
            float2 hv = *h;
            v00 = acc[nt][0] + bb.x + hv.x;
            v01 = acc[nt][1] + bb.y + hv.y;
            h->x = v00; h->y = v01;
        }
        if (r1 < NN) {
            float2* h = (float2*)&g_hv[(size_t)r1 * H + c];
            float2 hv = *h;
            v10 = acc[nt][2] + bb.x + hv.x;
            v11 = acc[nt][3] + bb.y + hv.y;
            h->x = v10; h->y = v11;
        }
        float s0 = v00 + v10, s1 = v01 + v11;
        float ss0 = v00 * v00 + v10 * v10, ss1 = v01 * v01 + v11 * v11;
#pragma unroll
        for (int off = 16; off >= 4; off >>= 1) {
            s0  += __shfl_down_sync(0xffffffffu, s0,  off);
            s1  += __shfl_down_sync(0xffffffffu, s1,  off);
            ss0 += __shfl_down_sync(0xffffffffu, ss0, off);
            ss1 += __shfl_down_sync(0xffffffffu, ss1, off);
        }
        if (tq == 0) {
            sm_s [warp * 128 + c]     = s0;
            sm_s [warp * 128 + c + 1] = s1;
            sm_ss[warp * 128 + c]     = ss0;
            sm_ss[warp * 128 + c + 1] = ss1;
        }
    }
    __syncthreads();
    if (tid < 128) {
        float s = 0.f, ss = 0.f;
#pragma unroll
        for (int w = 0; w < 8; w++) { s += sm_s[w * 128 + tid]; ss += sm_ss[w * 128 + tid]; }
        g_part[0][blockIdx.x][tid] = s;
        g_part[1][blockIdx.x][tid] = ss;
    }
    if (l < NL - 1) {
        __syncthreads();
        if (tid == 0) {
            __threadfence();
            int old = atomicAdd(&g_sync[1 + l], 1);
            flagg = (old == NBC - 1);
        }
        __syncthreads();
        if (flagg) bnfin_body(gamma, bnb, ee0, ee1, l + 1, (float*)As);
    }
}

// ---------------- graph pooling; last block does the output head -------------
__global__ void k_pool(const int* __restrict__ gid, const float* __restrict__ Wo,
                       const float* __restrict__ bo, float* __restrict__ out) {
    __shared__ int flag;
    int b = blockIdx.x, c = threadIdx.x;
    int n0 = b * BN_CHUNK;
    int n1 = min(NN, n0 + BN_CHUNK);
    float acc = 0.f;
    int curg = gid[n0];
    int run = 0;
    for (int n = n0; n < n1; n++) {
        int g = gid[n];
        if (g != curg) {
            atomicAdd(&g_hg[curg * H + c], acc);
            if (c == 0) atomicAdd(&g_cntg[curg], run);
            acc = 0.f; run = 0; curg = g;
        }
        acc += g_hv[n * H + c];
        run++;
    }
    atomicAdd(&g_hg[curg * H + c], acc);
    if (c == 0) atomicAdd(&g_cntg[curg], run);
    if (c == 0) {
        __threadfence();
        int old = atomicAdd(&g_sync[4], 1);
        flag = (old == BN_BLOCKS - 1);
    }
    __syncthreads();
    if (flag) {
        for (int t = c; t < GG * OUTD; t += 128) {
            int g = t / OUTD, o = t % OUTD;
            float inv = 1.f / (float)g_cntg[g];
            float a = bo[o];
            for (int h = 0; h < H; h++) a += g_hg[g * H + h] * inv * Wo[h * OUTD + o];
            out[t] = a;
        }
    }
}

// ---------------- launch -----------------------------------------------------
extern "C" void kernel_launch(void* const* d_in, const int* in_sizes, int n_in,
                              void* d_out, int out_size) {
    const int* nf0  = (const int*)d_in[0];
    const int* nf1  = (const int*)d_in[1];
    const int* ef0  = (const int*)d_in[2];
    const int* ef1  = (const int*)d_in[3];
    const int* esrc = (const int*)d_in[4];
    const int* edst = (const int*)d_in[5];
    const int* gid  = (const int*)d_in[6];
    int base = (n_in > 7 && in_sizes[7] == 1) ? 8 : 7;
    const float* Wn0  = (const float*)d_in[base + 0];
    const float* Wn1  = (const float*)d_in[base + 1];
    const float* ee0  = (const float*)d_in[base + 2];
    const float* ee1  = (const float*)d_in[base + 3];
    const float* beta = (const float*)d_in[base + 4];
    const float* mlpW = (const float*)d_in[base + 5];
    const float* mlpb = (const float*)d_in[base + 6];
    const float* gam  = (const float*)d_in[base + 7];
    const float* bnb  = (const float*)d_in[base + 8];
    const float* Wo   = (const float*)d_in[base + 9];
    const float* bo   = (const float*)d_in[base + 10];
    float* out = (float*)d_out;

    __half* wh_ptr;
    cudaGetSymbolAddress((void**)&wh_ptr, g_wh);

    k_embed<<<NBC + 48, 128>>>(nf0, nf1, Wn0, Wn1, mlpW);
    k_count<<<NEB, 256>>>(edst);
    k_scan12<<<NSB, 256>>>();
    k_scan3<<<NSB, 256>>>();
    k_scatter<<<NEB + 1, 256>>>(esrc, edst, ef0, ef1, gam, bnb, ee0, ee1);

    for (int l = 0; l < NL; l++) {
        k_bnh<<<(NN * HV4 + 255) / 256, 256>>>();
        k_agg<<<(NN * 32 + 255) / 256, 256>>>(beta, l);
        k_gemm<<<NBC, 256>>>(wh_ptr + (size_t)l * H * H, mlpb + (size_t)l * H,
                             gam, bnb, ee0, ee1, l);
    }

    k_pool<<<BN_BLOCKS, 128>>>(gid, Wo, bo, out);
}

// round 12
// speedup vs baseline: 1.0114x; 1.0114x over previous
#include <cuda_runtime.h>
#include <cuda_fp16.h>
#include <cstdint>

#define NN 50000
#define NE 600000
#define H  128
#define HV4 32          // H/4
#define GG 16
#define OUTD 14
#define NL 3
#define GEN_EPS 1e-7f
#define BN_EPS  1e-5f
#define BN_BLOCKS 256
#define BN_CHUNK  196     // ceil(50000/256)
#define NBC 391           // ceil(NN/128)  (embed / gemm blocks)
#define NSB 196           // ceil(NN/256)  (scan blocks)
#define NEB 2344          // ceil(NE/256)
#define MAXPART 800
#define LOG2E 1.4426950408889634f

// ---------------- scratch (device globals; no allocation allowed) ------------
__device__ float  g_hv [NN * H];
__device__ __align__(16) uint2  g_xh [NN * HV4];   // x fp16 (GEMM A)
__device__ __align__(16) __half g_wh [NL * H * H]; // W^T fp16 [l][n][k]
__device__ int    g_cnt[NN];
__device__ int    g_off[NN];
__device__ int    g_bsum[NSB];
__device__ int    g_boff[NSB];
__device__ int    g_edge[NE];                 // packed: src | (f0*3+f1)<<16
__device__ float  g_part[2][MAXPART][H];
__device__ float  g_scale[H];
__device__ float  g_shift[H];
__device__ __align__(16) float g_etab[NL][18 * H]; // per-layer combined edge tables
__device__ float  g_hg[GG * H];
__device__ int    g_cntg[GG];
__device__ int    g_sync[8];

__device__ __forceinline__ uint32_t su32(const void* p) {
    uint32_t a;
    asm("{ .reg .u64 t; cvta.to.shared.u64 t, %1; cvt.u32.u64 %0, t; }" : "=r"(a) : "l"(p));
    return a;
}

// ------- BN finalize (scale/shift only; etab precomputed upfront) ------------
__device__ void bnfin_body(const float* __restrict__ gamma, const float* __restrict__ bnb,
                           int l, float* red) {
    int tid = threadIdx.x;
    int c = tid & 127, g = tid >> 7;
    float s = 0.f, ss = 0.f;
#pragma unroll 8
    for (int b = g; b < NBC; b += 2) { s += g_part[0][b][c]; ss += g_part[1][b][c]; }
    red[g * 128 + c]       = s;
    red[256 + g * 128 + c] = ss;
    __syncthreads();
    if (tid < H) {
        float S  = red[tid]       + red[128 + tid];
        float SS = red[256 + tid] + red[384 + tid];
        float mu  = S / (float)NN;
        float var = fmaxf(SS / (float)NN - mu * mu, 0.f);
        float sc  = rsqrtf(var + BN_EPS) * gamma[l * H + tid];
        g_scale[tid] = sc;
        g_shift[tid] = bnb[l * H + tid] - mu * sc;
    }
}

// ---- embed (+BN stats, g_cnt zero); spare blocks: W^T transpose, etabs ------
__global__ void k_embed(const int* __restrict__ f0, const int* __restrict__ f1,
                        const float* __restrict__ W0, const float* __restrict__ W1,
                        const float* __restrict__ W,
                        const float* __restrict__ ee0, const float* __restrict__ ee1) {
    int b = blockIdx.x, tid = threadIdx.x;
    if (b == 0 && tid < 8) g_sync[tid] = 0;
    if (b < NBC) {
        __shared__ int sf0[128], sf1[128];
        int c = tid;
        int n0 = b * 128;
        int cnt = min(128, NN - n0);
        if (c < cnt) {
            sf0[c] = f0[n0 + c]; sf1[c] = f1[n0 + c];
            g_cnt[n0 + c] = 0;
        }
        __syncthreads();
        float s = 0.f, ss = 0.f;
        for (int i = 0; i < cnt; i++) {
            float v = W0[sf0[i] * H + c] + W1[sf1[i] * H + c];
            g_hv[(n0 + i) * H + c] = v;
            s += v; ss += v * v;
        }
        g_part[0][b][c] = s;
        g_part[1][b][c] = ss;
    } else if (b < NBC + 48) {
        // W^T -> fp16: 48 tile-blocks (3 layers x 4x4 tiles of 32x32)
        __shared__ float t[32][33];
        int bi = b - NBC;
        int l = bi >> 4, r = bi & 15;
        int bk = r >> 2, bn = r & 3;
        int tx = tid & 31, ty = tid >> 5;
        const float* Wl = W + (size_t)l * H * H;
#pragma unroll
        for (int i = 0; i < 8; i++)
            t[ty + i * 4][tx] = Wl[(bk * 32 + ty + i * 4) * H + bn * 32 + tx];
        __syncthreads();
        __half* out = g_wh + (size_t)l * H * H;
#pragma unroll
        for (int i = 0; i < 8; i++)
            out[(bn * 32 + ty + i * 4) * H + bk * 32 + tx] = __float2half(t[tx][ty + i * 4]);
    } else {
        // per-layer combined edge tables (inputs only; independent of data flow)
        int l = b - (NBC + 48);
        for (int i = tid; i < 18 * H; i += 128) {
            int idx = i >> 7, cc = i & 127;
            int e0 = idx / 3, e1 = idx - e0 * 3;
            g_etab[l][i] = ee0[(l * 6 + e0) * H + cc] + ee1[(l * 3 + e1) * H + cc];
        }
    }
}

// ---------------- CSR build --------------------------------------------------
__global__ void k_count(const int* __restrict__ dst) {
    int e = blockIdx.x * blockDim.x + threadIdx.x;
    if (e < NE) atomicAdd(&g_cnt[dst[e]], 1);
    if (blockIdx.x == 0) {
        for (int i = threadIdx.x; i < GG * H; i += 256) g_hg[i] = 0.f;
        if (threadIdx.x < GG) g_cntg[threadIdx.x] = 0;
    }
}

__global__ void k_scan12() {
    __shared__ int wsum[8];
    __shared__ int sm[256];
    __shared__ int flag;
    int b = blockIdx.x, t = threadIdx.x;
    int idx = b * 256 + t;
    int v = (idx < NN) ? g_cnt[idx] : 0;
    int s = v;
    for (int d = 16; d > 0; d >>= 1) s += __shfl_down_sync(0xffffffffu, s, d);
    if ((t & 31) == 0) wsum[t >> 5] = s;
    __syncthreads();
    if (t == 0) {
        int bs = 0;
#pragma unroll
        for (int w = 0; w < 8; w++) bs += wsum[w];
        g_bsum[b] = bs;
        __threadfence();
        int old = atomicAdd(&g_sync[0], 1);
        flag = (old == NSB - 1);
    }
    __syncthreads();
    if (flag) {
        int v2 = (t < NSB) ? g_bsum[t] : 0;
        sm[t] = v2;
        __syncthreads();
        for (int d = 1; d < 256; d <<= 1) {
            int u = (t >= d) ? sm[t - d] : 0;
            __syncthreads();
            sm[t] += u;
            __syncthreads();
        }
        if (t < NSB) g_boff[t] = sm[t] - v2;
    }
}

__global__ void k_scan3() {
    __shared__ int wsum[8];
    int b = blockIdx.x, t = threadIdx.x;
    int idx = b * 256 + t;
    int v = (idx < NN) ? g_cnt[idx] : 0;
    int inc = v;
    for (int d = 1; d < 32; d <<= 1) {
        int u = __shfl_up_sync(0xffffffffu, inc, d);
        if ((t & 31) >= d) inc += u;
    }
    if ((t & 31) == 31) wsum[t >> 5] = inc;
    __syncthreads();
    int w = t >> 5;
    int woff = 0;
#pragma unroll
    for (int i = 0; i < 8; i++) if (i < w) woff += wsum[i];
    if (idx < NN) g_off[idx] = g_boff[b] + woff + inc - v;
}

// scatter edges (g_off as cursor) + layer-0 bnfin in the extra block ----------
__global__ void k_scatter(const int* __restrict__ src, const int* __restrict__ dst,
                          const int* __restrict__ f0, const int* __restrict__ f1,
                          const float* __restrict__ gamma, const float* __restrict__ bnb) {
    int b = blockIdx.x;
    if (b < NEB) {
        int e = b * 256 + threadIdx.x;
        if (e >= NE) return;
        int d = dst[e];
        int j = atomicAdd(&g_off[d], 1);
        g_edge[j] = src[e] | ((f0[e] * 3 + f1[e]) << 16);
    } else {
        __shared__ float red[512];
        bnfin_body(gamma, bnb, 0, red);
    }
}

// ---------------- GENConv aggregation: warp per dst node ---------------------
// BN fused: hv1 = relu(hv*sc+sh).  t = max(hv1+e, 0); x = exp2(t*c1+c2);
// agg = sum(t*x)/sum(x) + eps (exact identity);  x_out = hv1 + agg, fp16.
// etab read straight from global (9KB, L1-resident) — no smem staging.
__global__ void __launch_bounds__(256) k_agg(const float* __restrict__ beta, int l) {
    int tid  = threadIdx.x;
    int gt   = blockIdx.x * 256 + tid;
    int wid  = gt >> 5;
    int lane = tid & 31;
    if (wid >= NN) return;
    float c1 = beta[l] * LOG2E;
    float c2 = GEN_EPS * c1;
    int end = g_off[wid];
    int beg = end - g_cnt[wid];
    const float4* __restrict__ hv4 = (const float4*)g_hv;
    const float4* __restrict__ et4 = (const float4*)g_etab[l];
    float4 sc = ((const float4*)g_scale)[lane];
    float4 sh = ((const float4*)g_shift)[lane];
    float4 num = make_float4(0.f, 0.f, 0.f, 0.f);
    float4 den = make_float4(0.f, 0.f, 0.f, 0.f);
#define EDGE_ELEM(hc, ec, scc, shc, nc, dc) do {                          \
        float h1_ = fmaxf(fmaf(hc, scc, shc), 0.f);                       \
        float t_  = fmaxf(h1_ + (ec), 0.f);                               \
        float z_  = fmaf(t_, c1, c2);                                     \
        float x_;                                                         \
        asm("ex2.approx.f32 %0, %1;" : "=f"(x_) : "f"(z_));               \
        dc += x_; nc = fmaf(t_, x_, nc); } while (0)
#define EDGE_ONE(pe) do {                                                 \
        int src_ = (pe) & 0xFFFF;                                         \
        int idx_ = (pe) >> 16;                                            \
        float4 h_ = hv4[src_ * HV4 + lane];                               \
        float4 e_ = __ldg(&et4[idx_ * HV4 + lane]);                       \
        EDGE_ELEM(h_.x, e_.x, sc.x, sh.x, num.x, den.x);                  \
        EDGE_ELEM(h_.y, e_.y, sc.y, sh.y, num.y, den.y);                  \
        EDGE_ELEM(h_.z, e_.z, sc.z, sh.z, num.z, den.z);                  \
        EDGE_ELEM(h_.w, e_.w, sc.w, sh.w, num.w, den.w); } while (0)
    int j = beg;
    for (; j + 2 <= end; j += 2) {
        int pe0 = g_edge[j], pe1 = g_edge[j + 1];
        EDGE_ONE(pe0);
        EDGE_ONE(pe1);
    }
    if (j < end) { int pe0 = g_edge[j]; EDGE_ONE(pe0); }
    float4 hr = hv4[wid * HV4 + lane];
    float4 xo;
    xo.x = fmaxf(fmaf(hr.x, sc.x, sh.x), 0.f);
    xo.y = fmaxf(fmaf(hr.y, sc.y, sh.y), 0.f);
    xo.z = fmaxf(fmaf(hr.z, sc.z, sh.z), 0.f);
    xo.w = fmaxf(fmaf(hr.w, sc.w, sh.w), 0.f);
    if (end > beg) {
        xo.x += num.x / den.x + GEN_EPS;
        xo.y += num.y / den.y + GEN_EPS;
        xo.z += num.z / den.z + GEN_EPS;
        xo.w += num.w / den.w + GEN_EPS;
    }
    __half2 p0 = __floats2half2_rn(xo.x, xo.y);
    __half2 p1 = __floats2half2_rn(xo.z, xo.w);
    uint2 o;
    o.x = *(unsigned int*)&p0;
    o.y = *(unsigned int*)&p1;
    g_xh[wid * HV4 + lane] = o;
}

// --- MLP GEMM via HMMA: hv = x@W + b + hv, + BN stats, + next-layer bnfin ----
__global__ void __launch_bounds__(256) k_gemm(const __half* __restrict__ Wt,
                                              const float* __restrict__ bias,
                                              const float* __restrict__ gamma,
                                              const float* __restrict__ bnb,
                                              int l) {
    __shared__ __align__(16) __half As[128 * 72];
    __shared__ __align__(16) __half Bs[128 * 72];
    __shared__ int flagg;
    int tid = threadIdx.x;
    int warp = tid >> 5, lane = tid & 31;
    int row0 = blockIdx.x * 128;
    const __half* xh = (const __half*)g_xh;

    float acc[16][4];
#pragma unroll
    for (int t = 0; t < 16; t++)
#pragma unroll
        for (int j = 0; j < 4; j++) acc[t][j] = 0.f;

#pragma unroll
    for (int kk = 0; kk < H; kk += 64) {
#pragma unroll
        for (int i = 0; i < 4; i++) {
            int f = tid + i * 256;
            int r = f >> 3, c8 = f & 7;
            uint4 v = make_uint4(0, 0, 0, 0);
            if (row0 + r < NN) v = ((const uint4*)(xh + (size_t)(row0 + r) * H + kk))[c8];
            *(uint4*)&As[r * 72 + c8 * 8] = v;
            uint4 w = ((const uint4*)(Wt + r * H + kk))[c8];
            *(uint4*)&Bs[r * 72 + c8 * 8] = w;
        }
        __syncthreads();
        uint32_t a_row = su32(&As[(warp * 16 + (lane & 15)) * 72 + ((lane >> 4) * 8)]);
#pragma unroll
        for (int k = 0; k < 4; k++) {
            uint32_t a0, a1, a2, a3;
            asm volatile("ldmatrix.sync.aligned.m8n8.x4.shared.b16 {%0,%1,%2,%3}, [%4];"
                         : "=r"(a0), "=r"(a1), "=r"(a2), "=r"(a3)
                         : "r"(a_row + k * 32));
#pragma unroll
            for (int p = 0; p < 8; p++) {
                int brow = p * 16 + ((lane >> 4) << 3) + (lane & 7);
                int bcol = k * 16 + ((lane >> 3) & 1) * 8;
                uint32_t baddr = su32(&Bs[brow * 72 + bcol]);
                uint32_t b0, b1, b2, b3;
                asm volatile("ldmatrix.sync.aligned.m8n8.x4.shared.b16 {%0,%1,%2,%3}, [%4];"
                             : "=r"(b0), "=r"(b1), "=r"(b2), "=r"(b3)
                             : "r"(baddr));
                asm volatile("mma.sync.aligned.m16n8k16.row.col.f32.f16.f16.f32 "
                             "{%0,%1,%2,%3}, {%4,%5,%6,%7}, {%8,%9}, {%0,%1,%2,%3};"
                             : "+f"(acc[2 * p][0]), "+f"(acc[2 * p][1]),
                               "+f"(acc[2 * p][2]), "+f"(acc[2 * p][3])
                             : "r"(a0), "r"(a1), "r"(a2), "r"(a3), "r"(b0), "r"(b1));
                asm volatile("mma.sync.aligned.m16n8k16.row.col.f32.f16.f16.f32 "
                             "{%0,%1,%2,%3}, {%4,%5,%6,%7}, {%8,%9}, {%0,%1,%2,%3};"
                             : "+f"(acc[2 * p + 1][0]), "+f"(acc[2 * p + 1][1]),
                               "+f"(acc[2 * p + 1][2]), "+f"(acc[2 * p + 1][3])
                             : "r"(a0), "r"(a1), "r"(a2), "r"(a3), "r"(b2), "r"(b3));
            }
        }
        __syncthreads();
    }
    float* sm_s  = (float*)As;
    float* sm_ss = (float*)Bs;
    int q = lane & 3, tq = lane >> 2;
    int r0 = row0 + warp * 16 + tq;
    int r1 = r0 + 8;
#pragma unroll
    for (int nt = 0; nt < 16; nt++) {
        int c = nt * 8 + 2 * q;
        float2 bb = *(const float2*)&bias[c];
        float v00 = 0.f, v01 = 0.f, v10 = 0.f, v11 = 0.f;
        if (r0 < NN) {
            float2* h = (float2*)&g_hv[(size_t)r0 * H + c];
            float2 hv = *h;
            v00 = acc[nt][0] + bb.x + hv.x;
            v01 = acc[nt][1] + bb.y + hv.y;
            h->x = v00; h->y = v01;
        }
        if (r1 < NN) {
            float2* h = (float2*)&g_hv[(size_t)r1 * H + c];
            float2 hv = *h;
            v10 = acc[nt][2] + bb.x + hv.x;
            v11 = acc[nt][3] + bb.y + hv.y;
            h->x = v10; h->y = v11;
        }
        float s0 = v00 + v10, s1 = v01 + v11;
        float ss0 = v00 * v00 + v10 * v10, ss1 = v01 * v01 + v11 * v11;
#pragma unroll
        for (int off = 16; off >= 4; off >>= 1) {
            s0  += __shfl_down_sync(0xffffffffu, s0,  off);
            s1  += __shfl_down_sync(0xffffffffu, s1,  off);
            ss0 += __shfl_down_sync(0xffffffffu, ss0, off);
            ss1 += __shfl_down_sync(0xffffffffu, ss1, off);
        }
        if (tq == 0) {
            sm_s [warp * 128 + c]     = s0;
            sm_s [warp * 128 + c + 1] = s1;
            sm_ss[warp * 128 + c]     = ss0;
            sm_ss[warp * 128 + c + 1] = ss1;
        }
    }
    __syncthreads();
    if (tid < 128) {
        float s = 0.f, ss = 0.f;
#pragma unroll
        for (int w = 0; w < 8; w++) { s += sm_s[w * 128 + tid]; ss += sm_ss[w * 128 + tid]; }
        g_part[0][blockIdx.x][tid] = s;
        g_part[1][blockIdx.x][tid] = ss;
    }
    if (l < NL - 1) {
        __syncthreads();
        if (tid == 0) {
            __threadfence();
            int old = atomicAdd(&g_sync[1 + l], 1);
            flagg = (old == NBC - 1);
        }
        __syncthreads();
        if (flagg) bnfin_body(gamma, bnb, l + 1, (float*)As);
    }
}

// ---------------- graph pooling; last block does the output head -------------
__global__ void k_pool(const int* __restrict__ gid, const float* __restrict__ Wo,
                       const float* __restrict__ bo, float* __restrict__ out) {
    __shared__ int flag;
    int b = blockIdx.x, c = threadIdx.x;
    int n0 = b * BN_CHUNK;
    int n1 = min(NN, n0 + BN_CHUNK);
    float acc = 0.f;
    int curg = gid[n0];
    int run = 0;
    for (int n = n0; n < n1; n++) {
        int g = gid[n];
        if (g != curg) {
            atomicAdd(&g_hg[curg * H + c], acc);
            if (c == 0) atomicAdd(&g_cntg[curg], run);
            acc = 0.f; run = 0; curg = g;
        }
        acc += g_hv[n * H + c];
        run++;
    }
    atomicAdd(&g_hg[curg * H + c], acc);
    if (c == 0) atomicAdd(&g_cntg[curg], run);
    if (c == 0) {
        __threadfence();
        int old = atomicAdd(&g_sync[4], 1);
        flag = (old == BN_BLOCKS - 1);
    }
    __syncthreads();
    if (flag) {
        for (int t = c; t < GG * OUTD; t += 128) {
            int g = t / OUTD, o = t % OUTD;
            float inv = 1.f / (float)g_cntg[g];
            float a = bo[o];
            for (int h = 0; h < H; h++) a += g_hg[g * H + h] * inv * Wo[h * OUTD + o];
            out[t] = a;
        }
    }
}

// ---------------- launch -----------------------------------------------------
extern "C" void kernel_launch(void* const* d_in, const int* in_sizes, int n_in,
                              void* d_out, int out_size) {
    const int* nf0  = (const int*)d_in[0];
    const int* nf1  = (const int*)d_in[1];
    const int* ef0  = (const int*)d_in[2];
    const int* ef1  = (const int*)d_in[3];
    const int* esrc = (const int*)d_in[4];
    const int* edst = (const int*)d_in[5];
    const int* gid  = (const int*)d_in[6];
    int base = (n_in > 7 && in_sizes[7] == 1) ? 8 : 7;
    const float* Wn0  = (const float*)d_in[base + 0];
    const float* Wn1  = (const float*)d_in[base + 1];
    const float* ee0  = (const float*)d_in[base + 2];
    const float* ee1  = (const float*)d_in[base + 3];
    const float* beta = (const float*)d_in[base + 4];
    const float* mlpW = (const float*)d_in[base + 5];
    const float* mlpb = (const float*)d_in[base + 6];
    const float* gam  = (const float*)d_in[base + 7];
    const float* bnb  = (const float*)d_in[base + 8];
    const float* Wo   = (const float*)d_in[base + 9];
    const float* bo   = (const float*)d_in[base + 10];
    float* out = (float*)d_out;

    __half* wh_ptr;
    cudaGetSymbolAddress((void**)&wh_ptr, g_wh);

    k_embed<<<NBC + 48 + NL, 128>>>(nf0, nf1, Wn0, Wn1, mlpW, ee0, ee1);
    k_count<<<NEB, 256>>>(edst);
    k_scan12<<<NSB, 256>>>();
    k_scan3<<<NSB, 256>>>();
    k_scatter<<<NEB + 1, 256>>>(esrc, edst, ef0, ef1, gam, bnb);

    for (int l = 0; l < NL; l++) {
        k_agg<<<(NN * 32 + 255) / 256, 256>>>(beta, l);
        k_gemm<<<NBC, 256>>>(wh_ptr + (size_t)l * H * H, mlpb + (size_t)l * H,
                             gam, bnb, l);
    }

    k_pool<<<BN_BLOCKS, 128>>>(gid, Wo, bo, out);
}